// round 1
// baseline (speedup 1.0000x reference)
#include <cuda_runtime.h>
#include <math.h>

// Problem dims
#define T_  128
#define B_  128
#define I_  128
#define H_  512
#define W_  16
#define G4  2048    // 4*H
#define BH  65536   // B*H
#define TB  16384   // T*B

// ---------------- device scratch (static; no allocation in kernel_launch) ----
__device__ float g_XWi[(size_t)TB * G4];     // x@Wi + (bi+ba), per (t,b)
__device__ float g_XQ [(size_t)TB * H_];     // x@Wq_x + bq
__device__ float g_WhWa[1024 * G4];          // [Wh;Wa] stacked rows
__device__ float g_bia[G4];                  // bi + ba
__device__ float g_h [BH];
__device__ float g_c [BH];
__device__ float g_HA[B_ * 1024];            // [h | attn] per batch row
__device__ float g_Vbuf[W_ * BH];            // V cache per buffer slot
__device__ float g_Qpart[4 * BH];            // split-K partials for Q
__device__ float g_Vpart[4 * BH];            // split-K partials for Vnew
__device__ float g_Pre [4 * B_ * G4];        // split-K partials for preact

// ---------------- generic fp32 tiled GEMM body: 64x64 tile, 256 thr, 4x4/thr
__device__ __forceinline__ void gemm_body(
    const float* __restrict__ A, int lda,
    const float* __restrict__ B, int ldb,
    float* __restrict__ C, int ldc,
    const float* __restrict__ bias,
    int m0, int n0, int nk)   // nk = Kslice/16
{
    __shared__ float As[2][16][68];
    __shared__ float Bs[2][16][64];
    const int tid = threadIdx.x;
    const int ar = tid >> 2;            // 0..63 (A row in tile)
    const int ac = (tid & 3) << 2;      // 0,4,8,12 (A k-col group)
    const int br = tid >> 4;            // 0..15 (B k-row)
    const int bc = (tid & 15) << 2;     // 0..60 (B col group)
    const float* Aptr = A + (size_t)(m0 + ar) * lda + ac;
    const float* Bptr = B + (size_t)br * ldb + n0 + bc;
    float4 ra = *(const float4*)Aptr;
    float4 rb = *(const float4*)Bptr;
    const int tm = (tid >> 4) << 2;     // 0..60
    const int tn = (tid & 15) << 2;     // 0..60
    float acc[4][4];
#pragma unroll
    for (int i = 0; i < 4; i++)
#pragma unroll
        for (int j = 0; j < 4; j++) acc[i][j] = 0.f;

    int buf = 0;
    for (int kt = 0; kt < nk; kt++) {
        As[buf][ac + 0][ar] = ra.x;
        As[buf][ac + 1][ar] = ra.y;
        As[buf][ac + 2][ar] = ra.z;
        As[buf][ac + 3][ar] = ra.w;
        *(float4*)&Bs[buf][br][bc] = rb;
        __syncthreads();
        if (kt + 1 < nk) {
            ra = *(const float4*)(Aptr + (kt + 1) * 16);
            rb = *(const float4*)(Bptr + (size_t)(kt + 1) * 16 * ldb);
        }
#pragma unroll
        for (int kk = 0; kk < 16; kk++) {
            float4 a = *(const float4*)(&As[buf][kk][tm]);
            float4 b = *(const float4*)(&Bs[buf][kk][tn]);
            acc[0][0] += a.x * b.x; acc[0][1] += a.x * b.y; acc[0][2] += a.x * b.z; acc[0][3] += a.x * b.w;
            acc[1][0] += a.y * b.x; acc[1][1] += a.y * b.y; acc[1][2] += a.y * b.z; acc[1][3] += a.y * b.w;
            acc[2][0] += a.z * b.x; acc[2][1] += a.z * b.y; acc[2][2] += a.z * b.z; acc[2][3] += a.z * b.w;
            acc[3][0] += a.w * b.x; acc[3][1] += a.w * b.y; acc[3][2] += a.w * b.z; acc[3][3] += a.w * b.w;
        }
        buf ^= 1;
    }
    float4 bv4 = make_float4(0.f, 0.f, 0.f, 0.f);
    if (bias) bv4 = *(const float4*)(bias + n0 + tn);
#pragma unroll
    for (int i = 0; i < 4; i++) {
        float4 v;
        v.x = acc[i][0] + bv4.x; v.y = acc[i][1] + bv4.y;
        v.z = acc[i][2] + bv4.z; v.w = acc[i][3] + bv4.w;
        *(float4*)&C[(size_t)(m0 + tm + i) * ldc + n0 + tn] = v;
    }
}

// ---------------- init: WhWa stack, bia, zero state, Vbuf = bv --------------
__global__ void k_init(const float* __restrict__ Wh, const float* __restrict__ Wa,
                       const float* __restrict__ bi, const float* __restrict__ ba,
                       const float* __restrict__ bv)
{
    int idx = blockIdx.x * blockDim.x + threadIdx.x;  // 0 .. 2M-1
    if (idx < 1024 * G4) {
        int r = idx / G4, j = idx % G4;
        g_WhWa[idx] = (r < H_) ? Wh[r * G4 + j] : Wa[(r - H_) * G4 + j];
    }
    if (idx < G4) g_bia[idx] = bi[idx] + ba[idx];
    if (idx < BH) { g_h[idx] = 0.f; g_c[idx] = 0.f; }
    if (idx < B_ * 1024) g_HA[idx] = 0.f;
    if (idx < W_ * BH) g_Vbuf[idx] = bv[idx & (H_ - 1)];
}

// ---------------- precompute GEMMs ------------------------------------------
__global__ void k_xwi(const float* __restrict__ x, const float* __restrict__ Wi)
{   // grid(32, 256): C = x(16384x128) @ Wi(128x2048) + (bi+ba)
    gemm_body(x, I_, Wi, G4, g_XWi, G4, g_bia, blockIdx.y * 64, blockIdx.x * 64, 8);
}
__global__ void k_xq(const float* __restrict__ x, const float* __restrict__ Wq,
                     const float* __restrict__ bq)
{   // grid(8, 256): C = x(16384x128) @ Wq[0:128,:](128x512) + bq
    gemm_body(x, I_, Wq, H_, g_XQ, H_, bq, blockIdx.y * 64, blockIdx.x * 64, 8);
}

// ---------------- per-step: Q = h@Wq_h (partials), Vnew = c@Wv (partials) ---
__global__ void k_qv(const float* __restrict__ Wq, const float* __restrict__ Wv)
{   // grid(8, 2, 8): z<4 -> Q slice z ; z>=4 -> V slice z-4 ; Kslice = 128
    int z = blockIdx.z;
    const float* A; const float* B; float* C; int s;
    if (z < 4) { s = z;     A = g_h; B = Wq + I_ * H_; C = g_Qpart + (size_t)s * BH; }
    else       { s = z - 4; A = g_c; B = Wv;           C = g_Vpart + (size_t)s * BH; }
    gemm_body(A + s * 128, H_, B + (size_t)s * 128 * H_, H_, C, H_, 0,
              blockIdx.y * 64, blockIdx.x * 64, 8);
}

// ---------------- per-step: attention (reduce partials, softmax, attn) ------
__global__ void k_attn(int t, const float* __restrict__ bv)
{   // grid(128), block(128): one CTA per batch row
    int b = blockIdx.x, tid = threadIdx.x;
    __shared__ float Qs[H_], Vt[H_], sc[W_];
    const int slot = t & (W_ - 1);
    const int nv = (t + 1 < W_) ? (t + 1) : W_;

    for (int k = tid; k < H_; k += 128) {
        float q = g_XQ[((size_t)t * B_ + b) * H_ + k];
        float v = bv[k];
#pragma unroll
        for (int s = 0; s < 4; s++) {
            q += g_Qpart[((size_t)s * B_ + b) * H_ + k];
            v += g_Vpart[((size_t)s * B_ + b) * H_ + k];
        }
        Qs[k] = q; Vt[k] = v;
        g_Vbuf[((size_t)slot * B_ + b) * H_ + k] = v;
    }
    __syncthreads();

    int w = tid >> 3, l8 = tid & 7;
    float s = 0.f;
    if (w < nv) {
        const float* Vw = (w == slot) ? Vt : &g_Vbuf[((size_t)w * B_ + b) * H_];
        for (int k = l8; k < H_; k += 8) s += Qs[k] * Vw[k];
    }
    s += __shfl_xor_sync(0xffffffffu, s, 4);
    s += __shfl_xor_sync(0xffffffffu, s, 2);
    s += __shfl_xor_sync(0xffffffffu, s, 1);
    if (l8 == 0 && w < nv) sc[w] = s * 0.04419417382415922f;   // 1/sqrt(512)
    __syncthreads();

    if (tid == 0) {
        float m = -1e30f;
        for (int i = 0; i < nv; i++) m = fmaxf(m, sc[i]);
        float p[W_]; float d = 0.f;
        for (int i = 0; i < nv; i++) { p[i] = expf(sc[i] - m); d += p[i]; }
        float inv = 1.f / d;
        for (int i = 0; i < W_; i++) sc[i] = (i < nv) ? p[i] * inv : 0.f;
    }
    __syncthreads();

    for (int k = tid; k < H_; k += 128) {
        float a = 0.f;
        for (int w2 = 0; w2 < nv; w2++) {
            float vv = (w2 == slot) ? Vt[k] : g_Vbuf[((size_t)w2 * B_ + b) * H_ + k];
            a += sc[w2] * vv;
        }
        g_HA[b * 1024 + H_ + k] = a;
    }
}

// ---------------- per-step: preact = [h|attn] @ [Wh;Wa] (split-K partials) --
__global__ void k_pre()
{   // grid(32, 2, 4): Kslice = 256
    int z = blockIdx.z;
    gemm_body(g_HA + z * 256, 1024, g_WhWa + (size_t)z * 256 * G4, G4,
              g_Pre + (size_t)z * B_ * G4, G4, 0,
              blockIdx.y * 64, blockIdx.x * 64, 16);
}

// ---------------- per-step: gates, cell update, output ----------------------
__global__ void k_cell(int t, float* __restrict__ out)
{   // grid(256), block(256): 65536 threads, one per (b,k)
    int idx = blockIdx.x * blockDim.x + threadIdx.x;
    int b = idx >> 9, k = idx & (H_ - 1);
    const float* xw = &g_XWi[((size_t)t * B_ + b) * G4];
    float pi = xw[k], pf = xw[k + 512], po = xw[k + 1024], pg = xw[k + 1536];
#pragma unroll
    for (int s = 0; s < 4; s++) {
        const float* pp = &g_Pre[((size_t)s * B_ + b) * G4];
        pi += pp[k]; pf += pp[k + 512]; po += pp[k + 1024]; pg += pp[k + 1536];
    }
    float ig = 1.f / (1.f + expf(-pi));
    float fg = 1.f / (1.f + expf(-pf));
    float og = 1.f / (1.f + expf(-po));
    float gg = tanhf(pg);
    float cn = g_c[idx] * fg + ig * gg;
    float hn = og * tanhf(cn);
    g_c[idx] = cn;
    g_h[idx] = hn;
    g_HA[b * 1024 + k] = hn;
    out[(size_t)t * BH + idx] = hn;
}

// ---------------- launch ----------------------------------------------------
extern "C" void kernel_launch(void* const* d_in, const int* in_sizes, int n_in,
                              void* d_out, int out_size)
{
    const float* x  = (const float*)d_in[0];
    const float* Wi = (const float*)d_in[1];
    const float* bi = (const float*)d_in[2];
    const float* Wh = (const float*)d_in[3];
    const float* Wv = (const float*)d_in[4];
    const float* bv = (const float*)d_in[5];
    const float* Wq = (const float*)d_in[6];
    const float* bq = (const float*)d_in[7];
    const float* Wa = (const float*)d_in[8];
    const float* ba = (const float*)d_in[9];
    float* out = (float*)d_out;

    k_init<<<8192, 256>>>(Wh, Wa, bi, ba, bv);
    k_xwi<<<dim3(32, 256, 1), 256>>>(x, Wi);
    k_xq <<<dim3(8, 256, 1), 256>>>(x, Wq, bq);

    for (int t = 0; t < T_; t++) {
        k_qv  <<<dim3(8, 2, 8), 256>>>(Wq, Wv);
        k_attn<<<128, 128>>>(t, bv);
        k_pre <<<dim3(32, 2, 4), 256>>>();
        k_cell<<<256, 256>>>(t, out);
    }
}